// round 1
// baseline (speedup 1.0000x reference)
#include <cuda_runtime.h>
#include <math.h>

// Problem constants (fixed by the reference)
#define V_SZ 400000
#define S_SZ 4096
#define D_SZ 300
#define C_SZ 4
#define GB   128            // gather blocks
#define ROWS (S_SZ / GB)    // 32 rows per gather block

// Scratch (device globals; no allocation allowed)
__device__ float g_part1[D_SZ * GB];   // per-block partial sums for dense, layout [d][block]
__device__ float g_part2[D_SZ * GB];   // per-block partial sums for addition
__device__ float g_mid[D_SZ];
__device__ float g_t[D_SZ];
__device__ float g_scores[S_SZ];
__device__ float g_reward[S_SZ];

// ---------------------------------------------------------------------------
// K1 / K5: gather embedding rows, (optionally weighted) accumulate per block.
// Partials written transposed: g_part[d * GB + blockIdx] for coalesced reduce.
// ---------------------------------------------------------------------------
template <bool WEIGHTED>
__global__ void k_gather(const int* __restrict__ x,
                         const float* __restrict__ emb,
                         float* __restrict__ part)
{
    __shared__ float acc[D_SZ];
    for (int d = threadIdx.x; d < D_SZ; d += blockDim.x) acc[d] = 0.0f;
    __syncthreads();

    const int r0 = blockIdx.x * ROWS;

    #pragma unroll 1
    for (int r = 0; r < ROWS; r += 4) {
        const float* b0 = emb + (size_t)x[r0 + r + 0] * D_SZ;
        const float* b1 = emb + (size_t)x[r0 + r + 1] * D_SZ;
        const float* b2 = emb + (size_t)x[r0 + r + 2] * D_SZ;
        const float* b3 = emb + (size_t)x[r0 + r + 3] * D_SZ;
        float w0 = 1.0f, w1 = 1.0f, w2 = 1.0f, w3 = 1.0f;
        if (WEIGHTED) {
            w0 = g_reward[r0 + r + 0];
            w1 = g_reward[r0 + r + 1];
            w2 = g_reward[r0 + r + 2];
            w3 = g_reward[r0 + r + 3];
        }
        for (int d = threadIdx.x; d < D_SZ; d += blockDim.x) {
            float v = acc[d];
            v = fmaf(w0, b0[d], v);
            v = fmaf(w1, b1[d], v);
            v = fmaf(w2, b2[d], v);
            v = fmaf(w3, b3[d], v);
            acc[d] = v;
        }
    }
    __syncthreads();
    for (int d = threadIdx.x; d < D_SZ; d += blockDim.x)
        part[(size_t)d * GB + blockIdx.x] = acc[d];
}

__device__ __forceinline__ float warp_sum(float p) {
    #pragma unroll
    for (int o = 16; o > 0; o >>= 1) p += __shfl_down_sync(0xFFFFFFFFu, p, o);
    return p;
}

// ---------------------------------------------------------------------------
// K2: reduce dense partials, mid = W1*dense + b1, t = Wb*mid. Single block.
// ---------------------------------------------------------------------------
__global__ void k_mlp(const float* __restrict__ W1, const float* __restrict__ b1,
                      const float* __restrict__ Wb)
{
    __shared__ float s_dense[D_SZ];
    __shared__ float s_mid[D_SZ];
    const int lane = threadIdx.x & 31;
    const int warp = threadIdx.x >> 5;   // 32 warps (blockDim = 1024)

    // Reduce 128 partials per d (coalesced: lane reads 4 consecutive chunks)
    for (int d = warp; d < D_SZ; d += 32) {
        const float* p = &g_part1[(size_t)d * GB];
        float v = p[lane] + p[lane + 32] + p[lane + 64] + p[lane + 96];
        v = warp_sum(v);
        if (lane == 0) s_dense[d] = v * (1.0f / S_SZ);
    }
    __syncthreads();

    // mid = W1 * dense + b1 (warp per row)
    for (int r = warp; r < D_SZ; r += 32) {
        const float* w = W1 + (size_t)r * D_SZ;
        float p = 0.0f;
        for (int e = lane; e < D_SZ; e += 32) p = fmaf(w[e], s_dense[e], p);
        p = warp_sum(p);
        if (lane == 0) s_mid[r] = p + b1[r];
    }
    __syncthreads();

    // t = Wb * mid (warp per row)
    for (int r = warp; r < D_SZ; r += 32) {
        const float* w = Wb + (size_t)r * D_SZ;
        float p = 0.0f;
        for (int e = lane; e < D_SZ; e += 32) p = fmaf(w[e], s_mid[e], p);
        p = warp_sum(p);
        if (lane == 0) g_t[r] = p;
    }
    __syncthreads();
    for (int d = threadIdx.x; d < D_SZ; d += blockDim.x) g_mid[d] = s_mid[d];
}

// ---------------------------------------------------------------------------
// K3: scores[s] = embed[s] . t + bb   (second gather pass, L2-resident)
// ---------------------------------------------------------------------------
__global__ void k_scores(const int* __restrict__ x, const float* __restrict__ emb,
                         const float* __restrict__ bb)
{
    __shared__ float st[D_SZ];
    for (int d = threadIdx.x; d < D_SZ; d += blockDim.x) st[d] = g_t[d];
    __syncthreads();

    const int lane   = threadIdx.x & 31;
    const int gwarp  = (blockIdx.x * blockDim.x + threadIdx.x) >> 5;
    const int nwarps = (gridDim.x * blockDim.x) >> 5;
    const float bias = bb[0];

    for (int s = gwarp; s < S_SZ; s += nwarps) {
        const float* base = emb + (size_t)x[s] * D_SZ;
        float p = 0.0f;
        for (int d = lane; d < D_SZ; d += 32) p = fmaf(base[d], st[d], p);
        p = warp_sum(p);
        if (lane == 0) g_scores[s] = p + bias;
    }
}

// ---------------------------------------------------------------------------
// K4: softmax over 4096 scores; write reward to output and keep a copy.
// Single block of 1024, 4 elements per thread. Fixed reduction order.
// ---------------------------------------------------------------------------
__global__ void k_softmax(float* __restrict__ reward_out)
{
    __shared__ float red[32];
    const int tid  = threadIdx.x;
    const int lane = tid & 31;
    const int warp = tid >> 5;

    float v[4];
    float m = -3.4e38f;
    #pragma unroll
    for (int i = 0; i < 4; i++) {
        v[i] = g_scores[tid + i * 1024];
        m = fmaxf(m, v[i]);
    }
    #pragma unroll
    for (int o = 16; o > 0; o >>= 1) m = fmaxf(m, __shfl_xor_sync(0xFFFFFFFFu, m, o));
    if (lane == 0) red[warp] = m;
    __syncthreads();
    float bm = red[lane];
    #pragma unroll
    for (int o = 16; o > 0; o >>= 1) bm = fmaxf(bm, __shfl_xor_sync(0xFFFFFFFFu, bm, o));

    float s = 0.0f;
    #pragma unroll
    for (int i = 0; i < 4; i++) {
        v[i] = expf(v[i] - bm);
        s += v[i];
    }
    #pragma unroll
    for (int o = 16; o > 0; o >>= 1) s += __shfl_xor_sync(0xFFFFFFFFu, s, o);
    __syncthreads();
    if (lane == 0) red[warp] = s;
    __syncthreads();
    float bs = red[lane];
    #pragma unroll
    for (int o = 16; o > 0; o >>= 1) bs += __shfl_xor_sync(0xFFFFFFFFu, bs, o);

    const float inv = 1.0f / bs;
    #pragma unroll
    for (int i = 0; i < 4; i++) {
        float r = v[i] * inv;
        reward_out[tid + i * 1024] = r;
        g_reward[tid + i * 1024]   = r;
    }
}

// ---------------------------------------------------------------------------
// K6: addition = reduce(part2)/S; out[c] = W2[c,:].(mid+addition) + b2[c]
// ---------------------------------------------------------------------------
__global__ void k_final(const float* __restrict__ W2, const float* __restrict__ b2,
                        float* __restrict__ out)
{
    __shared__ float s_v[D_SZ];
    const int lane = threadIdx.x & 31;
    const int warp = threadIdx.x >> 5;   // 32 warps

    for (int d = warp; d < D_SZ; d += 32) {
        const float* p = &g_part2[(size_t)d * GB];
        float v = p[lane] + p[lane + 32] + p[lane + 64] + p[lane + 96];
        v = warp_sum(v);
        if (lane == 0) s_v[d] = g_mid[d] + v * (1.0f / S_SZ);
    }
    __syncthreads();

    if (warp < C_SZ) {
        const float* w = W2 + (size_t)warp * D_SZ;
        float p = 0.0f;
        for (int d = lane; d < D_SZ; d += 32) p = fmaf(s_v[d], w[d], p);
        p = warp_sum(p);
        if (lane == 0) out[warp] = p + b2[warp];
    }
}

// ---------------------------------------------------------------------------
extern "C" void kernel_launch(void* const* d_in, const int* in_sizes, int n_in,
                              void* d_out, int out_size)
{
    const int*   x   = (const int*)  d_in[0];
    const float* emb = (const float*)d_in[1];
    const float* W1  = (const float*)d_in[2];
    const float* b1  = (const float*)d_in[3];
    const float* Wb  = (const float*)d_in[4];
    const float* bb  = (const float*)d_in[5];
    const float* W2  = (const float*)d_in[6];
    const float* b2  = (const float*)d_in[7];
    float* out = (float*)d_out;     // out[0:4] = output, out[4:4100] = reward

    float* part1; cudaGetSymbolAddress((void**)&part1, g_part1);
    float* part2; cudaGetSymbolAddress((void**)&part2, g_part2);

    k_gather<false><<<GB, 256>>>(x, emb, part1);     // dense partials
    k_mlp<<<1, 1024>>>(W1, b1, Wb);                  // dense -> mid -> t
    k_scores<<<GB, 256>>>(x, emb, bb);               // bilinear scores
    k_softmax<<<1, 1024>>>(out + C_SZ);              // reward
    k_gather<true><<<GB, 256>>>(x, emb, part2);      // weighted partials
    k_final<<<1, 1024>>>(W2, b2, out);               // output logits
}